// round 1
// baseline (speedup 1.0000x reference)
#include <cuda_runtime.h>
#include <math.h>

#define N_TOT   8192
#define B_HALF  4096
#define D_DIM   256
#define BM      128
#define BN      128
#define BK      32
#define JSPLIT  8
#define JCHUNK  (N_TOT / JSPLIT)   // 1024 columns per block in y
#define INV_T   2.0f               // 1 / TEMPERATURE
#define SIM_MAX 2.0f               // cos<=1 => sim<=2 exactly

// Scratch (no allocations allowed in kernel_launch)
__device__ float g_zn[N_TOT * D_DIM];            // normalized rows, 8 MB
__device__ float g_s[JSPLIT * N_TOT];            // partial sum exp(sim-2) per row
__device__ float g_pos[JSPLIT * N_TOT];          // partial positive logit per row

// ---------------------------------------------------------------------------
// Kernel 1: L2-normalize rows of [z_i ; z_j] into g_zn. One warp per row.
// ---------------------------------------------------------------------------
__global__ void normalize_kernel(const float* __restrict__ zi,
                                 const float* __restrict__ zj) {
    int row  = blockIdx.x * blockDim.y + threadIdx.y;   // blockDim = (32, 8)
    int lane = threadIdx.x;
    if (row >= N_TOT) return;

    const float* src = (row < B_HALF) ? (zi + (size_t)row * D_DIM)
                                      : (zj + (size_t)(row - B_HALF) * D_DIM);
    // 256 floats = 64 float4; 32 lanes * 2
    float4 v0 = reinterpret_cast<const float4*>(src)[lane];
    float4 v1 = reinterpret_cast<const float4*>(src)[lane + 32];

    float ss = v0.x * v0.x + v0.y * v0.y + v0.z * v0.z + v0.w * v0.w
             + v1.x * v1.x + v1.y * v1.y + v1.z * v1.z + v1.w * v1.w;
    #pragma unroll
    for (int o = 16; o > 0; o >>= 1)
        ss += __shfl_xor_sync(0xffffffffu, ss, o);

    float inv = 1.0f / fmaxf(sqrtf(ss), 1e-8f);

    float4* dst = reinterpret_cast<float4*>(&g_zn[(size_t)row * D_DIM]);
    v0.x *= inv; v0.y *= inv; v0.z *= inv; v0.w *= inv;
    v1.x *= inv; v1.y *= inv; v1.z *= inv; v1.w *= inv;
    dst[lane]      = v0;
    dst[lane + 32] = v1;
}

// ---------------------------------------------------------------------------
// Kernel 2: tiled Gram-matrix + streaming softmax-denominator accumulation.
// Block: 256 threads, computes BM x BN tiles; 8x8 micro-tile per thread with
// stride-16 row/col mapping (conflict-free scalar LDS).
// grid = (N_TOT/BM, JSPLIT); block (bx,by) covers rows [bx*128,+128) against
// columns [by*1024, +1024).
// ---------------------------------------------------------------------------
__global__ void __launch_bounds__(256, 2)
simloss_kernel() {
    __shared__ float As[BK][BM + 1];
    __shared__ float Bs[BK][BN + 1];

    const int iBase  = blockIdx.x * BM;
    const int jChunk = blockIdx.y * JCHUNK;
    const int t  = threadIdx.x;
    const int tx = t & 15;        // column group (16)
    const int ty = t >> 4;        // row group (16)

    float s_loc[8];
    float pos_loc[8];
    #pragma unroll
    for (int r = 0; r < 8; r++) { s_loc[r] = 0.0f; pos_loc[r] = 0.0f; }

    for (int jt = 0; jt < JCHUNK; jt += BN) {
        const int jBase = jChunk + jt;

        float acc[8][8];
        #pragma unroll
        for (int r = 0; r < 8; r++)
            #pragma unroll
            for (int c = 0; c < 8; c++) acc[r][c] = 0.0f;

        for (int kt = 0; kt < D_DIM; kt += BK) {
            // Load A and B tiles: 128 rows x 32 k each = 1024 float4 / tile.
            #pragma unroll
            for (int q = 0; q < 4; q++) {
                int idx = t + 256 * q;
                int r   = idx >> 3;       // row in tile
                int c4  = idx & 7;        // float4 column
                float4 va = *reinterpret_cast<const float4*>(
                    &g_zn[(size_t)(iBase + r) * D_DIM + kt + c4 * 4]);
                As[c4 * 4 + 0][r] = va.x;
                As[c4 * 4 + 1][r] = va.y;
                As[c4 * 4 + 2][r] = va.z;
                As[c4 * 4 + 3][r] = va.w;
                float4 vb = *reinterpret_cast<const float4*>(
                    &g_zn[(size_t)(jBase + r) * D_DIM + kt + c4 * 4]);
                Bs[c4 * 4 + 0][r] = vb.x;
                Bs[c4 * 4 + 1][r] = vb.y;
                Bs[c4 * 4 + 2][r] = vb.z;
                Bs[c4 * 4 + 3][r] = vb.w;
            }
            __syncthreads();

            #pragma unroll 8
            for (int k = 0; k < BK; k++) {
                float a[8], b[8];
                #pragma unroll
                for (int r = 0; r < 8; r++) a[r] = As[k][ty + 16 * r];
                #pragma unroll
                for (int c = 0; c < 8; c++) b[c] = Bs[k][tx + 16 * c];
                #pragma unroll
                for (int r = 0; r < 8; r++)
                    #pragma unroll
                    for (int c = 0; c < 8; c++)
                        acc[r][c] = fmaf(a[r], b[c], acc[r][c]);
            }
            __syncthreads();
        }

        // Epilogue: streaming accumulation of exp(sim - 2), positive capture.
        #pragma unroll
        for (int r = 0; r < 8; r++) {
            const int i = iBase + ty + 16 * r;
            const int jpos = (i + B_HALF) & (N_TOT - 1);
            #pragma unroll
            for (int c = 0; c < 8; c++) {
                const int j = jBase + tx + 16 * c;
                float sim = acc[r][c] * INV_T;
                if (j != i) s_loc[r] += __expf(sim - SIM_MAX);
                if (j == jpos) pos_loc[r] = sim;
            }
        }
    }

    // Reduce across the 16 tx threads sharing each row (half-warp shuffles).
    #pragma unroll
    for (int r = 0; r < 8; r++) {
        float s = s_loc[r];
        float p = pos_loc[r];
        #pragma unroll
        for (int o = 8; o > 0; o >>= 1) {
            s += __shfl_xor_sync(0xffffffffu, s, o, 16);
            p += __shfl_xor_sync(0xffffffffu, p, o, 16);
        }
        if (tx == 0) {
            const int i = iBase + ty + 16 * r;
            g_s[blockIdx.y * N_TOT + i]   = s;
            g_pos[blockIdx.y * N_TOT + i] = p;
        }
    }
}

// ---------------------------------------------------------------------------
// Kernel 3: deterministic final reduction -> mean(lse - pos).
// ---------------------------------------------------------------------------
__global__ void finalize_kernel(float* __restrict__ out) {
    __shared__ double red[256];
    const int t = threadIdx.x;
    double acc = 0.0;
    for (int i = t; i < N_TOT; i += 256) {
        float S = 0.0f, P = 0.0f;
        #pragma unroll
        for (int b = 0; b < JSPLIT; b++) {
            S += g_s[b * N_TOT + i];
            P += g_pos[b * N_TOT + i];
        }
        // lse = SIM_MAX + log(sum exp(sim - SIM_MAX)); loss_i = lse - pos_i
        acc += (double)(SIM_MAX + logf(S) - P);
    }
    red[t] = acc;
    __syncthreads();
    #pragma unroll
    for (int o = 128; o > 0; o >>= 1) {
        if (t < o) red[t] += red[t + o];
        __syncthreads();
    }
    if (t == 0) out[0] = (float)(red[0] / (double)N_TOT);
}

// ---------------------------------------------------------------------------
extern "C" void kernel_launch(void* const* d_in, const int* in_sizes, int n_in,
                              void* d_out, int out_size) {
    const float* zi = (const float*)d_in[0];
    const float* zj = (const float*)d_in[1];
    float* out = (float*)d_out;

    dim3 nblk(32, 8);
    normalize_kernel<<<N_TOT / 8, nblk>>>(zi, zj);

    dim3 grid(N_TOT / BM, JSPLIT);
    simloss_kernel<<<grid, 256>>>();

    finalize_kernel<<<1, 256>>>(out);
}

// round 4
// speedup vs baseline: 2.5034x; 2.5034x over previous
#include <cuda_runtime.h>
#include <cuda_bf16.h>
#include <cstdint>
#include <math.h>

#define N_TOT   8192
#define B_HALF  4096
#define D_DIM   256
#define BM      128
#define BN      128
#define BK      32
#define NKT     (D_DIM / BK)          // 8 k-tiles
#define NPART   ((N_TOT / BN) * 2)    // 128 partial slots (64 j-tiles x 2 warpN)
#define ROWB    80                    // padded smem row stride (64B data + 16B pad)

// ---------------- device scratch (no allocations allowed) -------------------
__device__ __align__(128) __nv_bfloat16 g_zbf[N_TOT * D_DIM];  // 4 MB normalized bf16
__device__ float g_s[NPART * N_TOT];    // partial sum exp(sim-2)
__device__ float g_pos[NPART * N_TOT];  // partial positive logit

// ---------------- helpers ----------------------------------------------------
__device__ __forceinline__ uint32_t smem_u32(const void* p) {
    uint32_t a;
    asm("{ .reg .u64 t; cvta.to.shared.u64 t, %1; cvt.u32.u64 %0, t; }"
        : "=r"(a) : "l"(p));
    return a;
}

__device__ __forceinline__ void ldmatrix_x4(uint32_t r[4], uint32_t addr) {
    asm volatile("ldmatrix.sync.aligned.m8n8.x4.shared.b16 {%0,%1,%2,%3}, [%4];"
                 : "=r"(r[0]), "=r"(r[1]), "=r"(r[2]), "=r"(r[3]) : "r"(addr));
}

__device__ __forceinline__ void mma16816(float c[4], const uint32_t a[4],
                                         uint32_t b0, uint32_t b1) {
    asm volatile(
        "mma.sync.aligned.m16n8k16.row.col.f32.bf16.bf16.f32 "
        "{%0,%1,%2,%3}, {%4,%5,%6,%7}, {%8,%9}, {%0,%1,%2,%3};"
        : "+f"(c[0]), "+f"(c[1]), "+f"(c[2]), "+f"(c[3])
        : "r"(a[0]), "r"(a[1]), "r"(a[2]), "r"(a[3]), "r"(b0), "r"(b1));
}

__device__ __forceinline__ void cp16(uint32_t saddr, const void* gaddr) {
    asm volatile("cp.async.ca.shared.global [%0], [%1], 16;"
                 :: "r"(saddr), "l"(gaddr));
}

// ---------------------------------------------------------------------------
// Kernel 1: L2-normalize rows of [z_i ; z_j] -> bf16 g_zbf. One warp per row.
// ---------------------------------------------------------------------------
__global__ void normalize_kernel(const float* __restrict__ zi,
                                 const float* __restrict__ zj) {
    int row  = blockIdx.x * blockDim.y + threadIdx.y;   // blockDim = (32, 8)
    int lane = threadIdx.x;
    if (row >= N_TOT) return;

    const float* src = (row < B_HALF) ? (zi + (size_t)row * D_DIM)
                                      : (zj + (size_t)(row - B_HALF) * D_DIM);
    float4 v0 = reinterpret_cast<const float4*>(src)[lane * 2 + 0];
    float4 v1 = reinterpret_cast<const float4*>(src)[lane * 2 + 1];

    float ss = v0.x * v0.x + v0.y * v0.y + v0.z * v0.z + v0.w * v0.w
             + v1.x * v1.x + v1.y * v1.y + v1.z * v1.z + v1.w * v1.w;
    #pragma unroll
    for (int o = 16; o > 0; o >>= 1)
        ss += __shfl_xor_sync(0xffffffffu, ss, o);

    float inv = 1.0f / fmaxf(sqrtf(ss), 1e-8f);

    __nv_bfloat162 b0 = __float22bfloat162_rn(make_float2(v0.x * inv, v0.y * inv));
    __nv_bfloat162 b1 = __float22bfloat162_rn(make_float2(v0.z * inv, v0.w * inv));
    __nv_bfloat162 b2 = __float22bfloat162_rn(make_float2(v1.x * inv, v1.y * inv));
    __nv_bfloat162 b3 = __float22bfloat162_rn(make_float2(v1.z * inv, v1.w * inv));
    uint4 packed;
    packed.x = *reinterpret_cast<uint32_t*>(&b0);
    packed.y = *reinterpret_cast<uint32_t*>(&b1);
    packed.z = *reinterpret_cast<uint32_t*>(&b2);
    packed.w = *reinterpret_cast<uint32_t*>(&b3);
    reinterpret_cast<uint4*>(g_zbf + (size_t)row * D_DIM)[lane] = packed;
}

// ---------------------------------------------------------------------------
// Kernel 2: bf16 HMMA Gram tile (128x128, K=256) with cp.async double buffer
// and fused softmax epilogue. 256 threads = 8 warps (4 in M x 2 in N).
// ---------------------------------------------------------------------------
__global__ void __launch_bounds__(256, 2) simloss_mma_kernel() {
    __shared__ __align__(16) uint8_t sA[2][BM * ROWB];   // 2 x 10240 B
    __shared__ __align__(16) uint8_t sB[2][BN * ROWB];

    const int t     = threadIdx.x;
    const int lane  = t & 31;
    const int wid   = t >> 5;
    const int warpM = wid & 3;    // 4 warps along M, 32 rows each
    const int warpN = wid >> 2;   // 2 warps along N, 64 cols each
    const int iBase = blockIdx.x * BM;
    const int jBase = blockIdx.y * BN;

    float acc[2][8][4];
    #pragma unroll
    for (int mt = 0; mt < 2; ++mt)
        #pragma unroll
        for (int nt = 0; nt < 8; ++nt)
            #pragma unroll
            for (int e = 0; e < 4; ++e) acc[mt][nt][e] = 0.0f;

    // ---- async tile loader: 128 rows x 64B for A and B, 16B per cp.async ----
    const int ldRow = t >> 2;          // 0..63 base row (thread does rows r, r+64)
    const int ldC   = t & 3;           // 16B chunk in row

    auto issue_load = [&](int stage, int kelem) {
        #pragma unroll
        for (int q = 0; q < 2; ++q) {
            int r = ldRow + q * 64;
            cp16(smem_u32(&sA[stage][r * ROWB + ldC * 16]),
                 g_zbf + (size_t)(iBase + r) * D_DIM + kelem + ldC * 8);
            cp16(smem_u32(&sB[stage][r * ROWB + ldC * 16]),
                 g_zbf + (size_t)(jBase + r) * D_DIM + kelem + ldC * 8);
        }
        asm volatile("cp.async.commit_group;");
    };

    issue_load(0, 0);

    for (int kt = 0; kt < NKT; ++kt) {
        if (kt + 1 < NKT) {
            issue_load((kt + 1) & 1, (kt + 1) * BK);
            asm volatile("cp.async.wait_group 1;" ::: "memory");
        } else {
            asm volatile("cp.async.wait_group 0;" ::: "memory");
        }
        __syncthreads();

        const int st = kt & 1;
        const uint32_t aBase = smem_u32(&sA[st][0]);
        const uint32_t bBase = smem_u32(&sB[st][0]);

        #pragma unroll
        for (int ks = 0; ks < 2; ++ks) {          // two k16 steps per BK=32
            const int kb = ks * 32;               // byte offset of k16 chunk
            uint32_t a[2][4];
            #pragma unroll
            for (int mt = 0; mt < 2; ++mt) {
                int row = warpM * 32 + mt * 16 + (lane & 15);
                ldmatrix_x4(a[mt], aBase + row * ROWB + kb + (lane >> 4) * 16);
            }
            uint32_t b[4][4];
            #pragma unroll
            for (int nq = 0; nq < 4; ++nq) {
                int row = warpN * 64 + nq * 16 + (lane & 15);
                ldmatrix_x4(b[nq], bBase + row * ROWB + kb + (lane >> 4) * 16);
            }
            #pragma unroll
            for (int mt = 0; mt < 2; ++mt)
                #pragma unroll
                for (int nt = 0; nt < 8; ++nt)
                    mma16816(acc[mt][nt], a[mt],
                             b[nt >> 1][nt & 1], b[nt >> 1][(nt & 1) + 2]);
        }
        __syncthreads();
    }

    // ---- fused epilogue: sim = 2*cos; max logit = 2 exactly (cos <= 1) ----
    float ssum[4] = {0.f, 0.f, 0.f, 0.f};
    float pos[4]  = {0.f, 0.f, 0.f, 0.f};
    const int r0 = lane >> 2;           // row-in-8 group
    const int c0 = (lane & 3) * 2;      // col pair base

    #pragma unroll
    for (int mt = 0; mt < 2; ++mt)
        #pragma unroll
        for (int h = 0; h < 2; ++h) {
            const int s = mt * 2 + h;
            const int i  = iBase + warpM * 32 + mt * 16 + h * 8 + r0;
            const int jp = (i + B_HALF) & (N_TOT - 1);
            #pragma unroll
            for (int nt = 0; nt < 8; ++nt)
                #pragma unroll
                for (int e = 0; e < 2; ++e) {
                    const int j = jBase + warpN * 64 + nt * 8 + c0 + e;
                    float sim = 2.0f * acc[mt][nt][h * 2 + e];
                    if (j != i)  ssum[s] += __expf(sim - 2.0f);
                    if (j == jp) pos[s] = sim;
                }
        }

    // reduce across the 4 lanes sharing each row
    #pragma unroll
    for (int s = 0; s < 4; ++s) {
        #pragma unroll
        for (int o = 1; o < 4; o <<= 1) {
            ssum[s] += __shfl_xor_sync(0xffffffffu, ssum[s], o);
            pos[s]  += __shfl_xor_sync(0xffffffffu, pos[s], o);
        }
    }
    if ((lane & 3) == 0) {
        const size_t slot = (size_t)(blockIdx.y * 2 + warpN) * N_TOT;
        #pragma unroll
        for (int s = 0; s < 4; ++s) {
            const int mt = s >> 1, h = s & 1;
            const int i = iBase + warpM * 32 + mt * 16 + h * 8 + r0;
            g_s[slot + i]   = ssum[s];
            g_pos[slot + i] = pos[s];
        }
    }
}

// ---------------------------------------------------------------------------
// Kernel 3: deterministic final reduction -> mean(lse - pos).
// ---------------------------------------------------------------------------
__global__ void finalize_kernel(float* __restrict__ out) {
    __shared__ double red[256];
    const int t = threadIdx.x;
    double acc = 0.0;
    for (int i = t; i < N_TOT; i += 256) {
        float S = 0.0f, P = 0.0f;
        #pragma unroll 8
        for (int b = 0; b < NPART; ++b) {
            S += g_s[(size_t)b * N_TOT + i];
            P += g_pos[(size_t)b * N_TOT + i];
        }
        acc += (double)(2.0f + logf(S) - P);   // lse = 2 + log(sum exp(sim-2))
    }
    red[t] = acc;
    __syncthreads();
    #pragma unroll
    for (int o = 128; o > 0; o >>= 1) {
        if (t < o) red[t] += red[t + o];
        __syncthreads();
    }
    if (t == 0) out[0] = (float)(red[0] / (double)N_TOT);
}

// ---------------------------------------------------------------------------
extern "C" void kernel_launch(void* const* d_in, const int* in_sizes, int n_in,
                              void* d_out, int out_size) {
    const float* zi = (const float*)d_in[0];
    const float* zj = (const float*)d_in[1];
    float* out = (float*)d_out;

    dim3 nblk(32, 8);
    normalize_kernel<<<N_TOT / 8, nblk>>>(zi, zj);

    dim3 grid(N_TOT / BM, N_TOT / BN);
    simloss_mma_kernel<<<grid, 256>>>();

    finalize_kernel<<<1, 256>>>(out);
}

// round 6
// speedup vs baseline: 5.0222x; 2.0062x over previous
#include <cuda_runtime.h>
#include <cuda_bf16.h>
#include <cstdint>
#include <math.h>

#define N_TOT   8192
#define B_HALF  4096
#define D_DIM   256
#define BM      128
#define BN      128
#define BK      32
#define NKT     (D_DIM / BK)          // 8 k-tiles
#define NTILE   64                    // 8192/128 tile blocks per dim
#define NPAIR   (NTILE * (NTILE + 1) / 2)   // 2080 upper-triangular tiles
#define ROWB    80                    // padded smem row stride (64B data + 16B pad)

// ---------------- device scratch (no allocations allowed) -------------------
__device__ __align__(128) __nv_bfloat16 g_zbf[N_TOT * D_DIM];  // 4 MB normalized bf16
__device__ float g_s[NTILE * N_TOT];   // partial sum exp(sim-2); slot = other tile idx
__device__ float g_posv[N_TOT];        // positive logit per row (one writer per elem)

// ---------------- helpers ----------------------------------------------------
__device__ __forceinline__ uint32_t smem_u32(const void* p) {
    uint32_t a;
    asm("{ .reg .u64 t; cvta.to.shared.u64 t, %1; cvt.u32.u64 %0, t; }"
        : "=r"(a) : "l"(p));
    return a;
}

__device__ __forceinline__ void ldmatrix_x4(uint32_t r[4], uint32_t addr) {
    asm volatile("ldmatrix.sync.aligned.m8n8.x4.shared.b16 {%0,%1,%2,%3}, [%4];"
                 : "=r"(r[0]), "=r"(r[1]), "=r"(r[2]), "=r"(r[3]) : "r"(addr));
}

__device__ __forceinline__ void mma16816(float c[4], const uint32_t a[4],
                                         uint32_t b0, uint32_t b1) {
    asm volatile(
        "mma.sync.aligned.m16n8k16.row.col.f32.bf16.bf16.f32 "
        "{%0,%1,%2,%3}, {%4,%5,%6,%7}, {%8,%9}, {%0,%1,%2,%3};"
        : "+f"(c[0]), "+f"(c[1]), "+f"(c[2]), "+f"(c[3])
        : "r"(a[0]), "r"(a[1]), "r"(a[2]), "r"(a[3]), "r"(b0), "r"(b1));
}

__device__ __forceinline__ void cp16(uint32_t saddr, const void* gaddr) {
    asm volatile("cp.async.ca.shared.global [%0], [%1], 16;"
                 :: "r"(saddr), "l"(gaddr));
}

// ---------------------------------------------------------------------------
// Kernel 1: L2-normalize rows of [z_i ; z_j] -> bf16 g_zbf. One warp per row.
// ---------------------------------------------------------------------------
__global__ void normalize_kernel(const float* __restrict__ zi,
                                 const float* __restrict__ zj) {
    int row  = blockIdx.x * blockDim.y + threadIdx.y;   // blockDim = (32, 8)
    int lane = threadIdx.x;
    if (row >= N_TOT) return;

    const float* src = (row < B_HALF) ? (zi + (size_t)row * D_DIM)
                                      : (zj + (size_t)(row - B_HALF) * D_DIM);
    float4 v0 = reinterpret_cast<const float4*>(src)[lane * 2 + 0];
    float4 v1 = reinterpret_cast<const float4*>(src)[lane * 2 + 1];

    float ss = v0.x * v0.x + v0.y * v0.y + v0.z * v0.z + v0.w * v0.w
             + v1.x * v1.x + v1.y * v1.y + v1.z * v1.z + v1.w * v1.w;
    #pragma unroll
    for (int o = 16; o > 0; o >>= 1)
        ss += __shfl_xor_sync(0xffffffffu, ss, o);

    float inv = 1.0f / fmaxf(sqrtf(ss), 1e-8f);

    __nv_bfloat162 b0 = __float22bfloat162_rn(make_float2(v0.x * inv, v0.y * inv));
    __nv_bfloat162 b1 = __float22bfloat162_rn(make_float2(v0.z * inv, v0.w * inv));
    __nv_bfloat162 b2 = __float22bfloat162_rn(make_float2(v1.x * inv, v1.y * inv));
    __nv_bfloat162 b3 = __float22bfloat162_rn(make_float2(v1.z * inv, v1.w * inv));
    uint4 packed;
    packed.x = *reinterpret_cast<uint32_t*>(&b0);
    packed.y = *reinterpret_cast<uint32_t*>(&b1);
    packed.z = *reinterpret_cast<uint32_t*>(&b2);
    packed.w = *reinterpret_cast<uint32_t*>(&b3);
    reinterpret_cast<uint4*>(g_zbf + (size_t)row * D_DIM)[lane] = packed;
}

// ---------------------------------------------------------------------------
// Kernel 2: symmetric bf16 HMMA Gram tiles (upper triangle only) + fused
// softmax epilogue contributing BOTH orientations of each off-diagonal tile.
// 256 threads = 8 warps (4 in M x 2 in N).
// ---------------------------------------------------------------------------
__global__ void __launch_bounds__(256, 2) simloss_mma_kernel() {
    __shared__ __align__(16) uint8_t sA[2][BM * ROWB];   // 2 x 10240 B
    __shared__ __align__(16) uint8_t sB[2][BN * ROWB];

    // Map linear block id -> upper-triangular tile pair (it <= jt)
    int q = blockIdx.x;
    int it = 0, start = 0;
    while (start + (NTILE - it) <= q) { start += NTILE - it; ++it; }
    const int jt = it + (q - start);

    const int t     = threadIdx.x;
    const int lane  = t & 31;
    const int wid   = t >> 5;
    const int warpM = wid & 3;    // 4 warps along M, 32 rows each
    const int warpN = wid >> 2;   // 2 warps along N, 64 cols each
    const int iBase = it * BM;
    const int jBase = jt * BN;

    float acc[2][8][4];
    #pragma unroll
    for (int mt = 0; mt < 2; ++mt)
        #pragma unroll
        for (int nt = 0; nt < 8; ++nt)
            #pragma unroll
            for (int e = 0; e < 4; ++e) acc[mt][nt][e] = 0.0f;

    const int ldRow = t >> 2;          // 0..63 base row (thread does rows r, r+64)
    const int ldC   = t & 3;           // 16B chunk in row

    auto issue_load = [&](int stage, int kelem) {
        #pragma unroll
        for (int qq = 0; qq < 2; ++qq) {
            int r = ldRow + qq * 64;
            cp16(smem_u32(&sA[stage][r * ROWB + ldC * 16]),
                 g_zbf + (size_t)(iBase + r) * D_DIM + kelem + ldC * 8);
            cp16(smem_u32(&sB[stage][r * ROWB + ldC * 16]),
                 g_zbf + (size_t)(jBase + r) * D_DIM + kelem + ldC * 8);
        }
        asm volatile("cp.async.commit_group;");
    };

    issue_load(0, 0);

    for (int kt = 0; kt < NKT; ++kt) {
        if (kt + 1 < NKT) {
            issue_load((kt + 1) & 1, (kt + 1) * BK);
            asm volatile("cp.async.wait_group 1;" ::: "memory");
        } else {
            asm volatile("cp.async.wait_group 0;" ::: "memory");
        }
        __syncthreads();

        const int st = kt & 1;
        const uint32_t aBase = smem_u32(&sA[st][0]);
        const uint32_t bBase = smem_u32(&sB[st][0]);

        #pragma unroll
        for (int ks = 0; ks < 2; ++ks) {          // two k16 steps per BK=32
            const int kb = ks * 32;               // byte offset of k16 chunk
            uint32_t a[2][4];
            #pragma unroll
            for (int mt = 0; mt < 2; ++mt) {
                int row = warpM * 32 + mt * 16 + (lane & 15);
                ldmatrix_x4(a[mt], aBase + row * ROWB + kb + (lane >> 4) * 16);
            }
            uint32_t b[4][4];
            #pragma unroll
            for (int nq = 0; nq < 4; ++nq) {
                int row = warpN * 64 + nq * 16 + (lane & 15);
                ldmatrix_x4(b[nq], bBase + row * ROWB + kb + (lane >> 4) * 16);
            }
            #pragma unroll
            for (int mt = 0; mt < 2; ++mt)
                #pragma unroll
                for (int nt = 0; nt < 8; ++nt)
                    mma16816(acc[mt][nt], a[mt],
                             b[nt >> 1][nt & 1], b[nt >> 1][(nt & 1) + 2]);
        }
        __syncthreads();
    }

    // ---- fused epilogue: sim = 2*cos; max logit = 2 exactly (cos <= 1) ----
    const int r0 = lane >> 2;           // row-in-8 group
    const int c0 = (lane & 3) * 2;      // col pair base

    float ssum[4]  = {0.f, 0.f, 0.f, 0.f};   // direct: per-row sums
    float csum[16];                           // transposed: per-col sums
    #pragma unroll
    for (int ci = 0; ci < 16; ++ci) csum[ci] = 0.0f;

    #pragma unroll
    for (int mt = 0; mt < 2; ++mt)
        #pragma unroll
        for (int h = 0; h < 2; ++h) {
            const int s = mt * 2 + h;
            const int i  = iBase + warpM * 32 + mt * 16 + h * 8 + r0;
            const int jp = (i + B_HALF) & (N_TOT - 1);
            #pragma unroll
            for (int nt = 0; nt < 8; ++nt)
                #pragma unroll
                for (int e = 0; e < 2; ++e) {
                    const int j = jBase + warpN * 64 + nt * 8 + c0 + e;
                    float sim = 2.0f * acc[mt][nt][h * 2 + e];
                    float ex  = __expf(sim - 2.0f);
                    if (j != i) ssum[s] += ex;
                    csum[nt * 2 + e] += ex;
                    if (j == jp) {                 // only fires for i < B_HALF
                        g_posv[i] = sim;           // single writer per element
                        g_posv[j] = sim;
                    }
                }
        }

    // direct: reduce across 4 lanes sharing each row
    #pragma unroll
    for (int s = 0; s < 4; ++s) {
        ssum[s] += __shfl_xor_sync(0xffffffffu, ssum[s], 1);
        ssum[s] += __shfl_xor_sync(0xffffffffu, ssum[s], 2);
    }
    // transposed: reduce across 8 lanes sharing each column
    #pragma unroll
    for (int ci = 0; ci < 16; ++ci) {
        csum[ci] += __shfl_xor_sync(0xffffffffu, csum[ci], 4);
        csum[ci] += __shfl_xor_sync(0xffffffffu, csum[ci], 8);
        csum[ci] += __shfl_xor_sync(0xffffffffu, csum[ci], 16);
    }

    // CTA-level combine in smem scratch (overlays sA; all mma reads done)
    float* dirS = reinterpret_cast<float*>(&sA[0][0]);       // [2][128]
    float* trS  = dirS + 2 * 128;                             // [4][128]

    if ((lane & 3) == 0) {
        #pragma unroll
        for (int s = 0; s < 4; ++s) {
            const int mt = s >> 1, h = s & 1;
            const int row = warpM * 32 + mt * 16 + h * 8 + r0;
            dirS[warpN * 128 + row] = ssum[s];
        }
    }
    if (lane < 4) {
        #pragma unroll
        for (int nt = 0; nt < 8; ++nt)
            #pragma unroll
            for (int e = 0; e < 2; ++e) {
                const int col = warpN * 64 + nt * 8 + (lane & 3) * 2 + e;
                trS[warpM * 128 + col] = csum[nt * 2 + e];
            }
    }
    __syncthreads();

    if (t < 128) {
        // direct partial: slot jt, rows iBase..iBase+127
        g_s[(size_t)jt * N_TOT + iBase + t] = dirS[t] + dirS[128 + t];
    } else if (it != jt) {
        // transposed partial: slot it, rows jBase..jBase+127
        const int c = t - 128;
        g_s[(size_t)it * N_TOT + jBase + c] =
            trS[c] + trS[128 + c] + trS[256 + c] + trS[384 + c];
    }
}

// ---------------------------------------------------------------------------
// Kernel 3: deterministic final reduction -> mean(lse - pos).
// ---------------------------------------------------------------------------
__global__ void finalize_kernel(float* __restrict__ out) {
    __shared__ double red[256];
    const int t = threadIdx.x;
    double acc = 0.0;
    for (int i = t; i < N_TOT; i += 256) {
        float S = 0.0f;
        #pragma unroll 8
        for (int b = 0; b < NTILE; ++b)
            S += g_s[(size_t)b * N_TOT + i];
        acc += (double)(2.0f + logf(S) - g_posv[i]);  // lse = 2 + log(sum exp(sim-2))
    }
    red[t] = acc;
    __syncthreads();
    #pragma unroll
    for (int o = 128; o > 0; o >>= 1) {
        if (t < o) red[t] += red[t + o];
        __syncthreads();
    }
    if (t == 0) out[0] = (float)(red[0] / (double)N_TOT);
}

// ---------------------------------------------------------------------------
extern "C" void kernel_launch(void* const* d_in, const int* in_sizes, int n_in,
                              void* d_out, int out_size) {
    const float* zi = (const float*)d_in[0];
    const float* zj = (const float*)d_in[1];
    float* out = (float*)d_out;

    dim3 nblk(32, 8);
    normalize_kernel<<<N_TOT / 8, nblk>>>(zi, zj);

    simloss_mma_kernel<<<NPAIR, 256>>>();

    finalize_kernel<<<1, 256>>>(out);
}